// round 1
// baseline (speedup 1.0000x reference)
#include <cuda_runtime.h>

#define NC       32
#define NSTEPS   32
#define DDIM     30
#define BLOCK    256
#define PPT      4    // points per thread

__global__ __launch_bounds__(BLOCK)
void cpab_kernel(const float* __restrict__ points,
                 const float* __restrict__ theta,
                 const float* __restrict__ basis,
                 float* __restrict__ out,
                 int n_points)
{
    __shared__ float sT00[NC];
    __shared__ float sT01[NC];

    const int t   = blockIdx.y;
    const int tid = threadIdx.x;

    // --- Per-block precompute of the 32 cell transforms for this theta ---
    if (tid < NC) {
        const float dT = 1.0f / (float)NSTEPS;
        const float* __restrict__ ba = basis + (2 * tid)     * DDIM;
        const float* __restrict__ bb = basis + (2 * tid + 1) * DDIM;
        const float* __restrict__ th = theta + t * DDIM;
        float a = 0.0f, b = 0.0f;
        #pragma unroll
        for (int j = 0; j < DDIM; ++j) {
            float tj = th[j];
            a = fmaf(ba[j], tj, a);
            b = fmaf(bb[j], tj, b);
        }
        a *= dT;
        b *= dT;
        float ea  = expf(a);
        // phi(a) = (e^a - 1)/a, stable small-a branch matching reference
        float phi = (fabsf(a) < 1e-6f) ? (1.0f + 0.5f * a) : (expm1f(a) / a);
        sT00[tid] = ea;
        sT01[tid] = b * phi;
    }
    __syncthreads();

    // --- Main integration: PPT points per thread for ILP ---
    const int base = blockIdx.x * (BLOCK * PPT) + tid;

    float x[PPT];
    #pragma unroll
    for (int k = 0; k < PPT; ++k) {
        int idx = base + k * BLOCK;
        x[k] = (idx < n_points) ? points[idx] : 0.0f;
    }

    #pragma unroll
    for (int s = 0; s < NSTEPS; ++s) {
        #pragma unroll
        for (int k = 0; k < PPT; ++k) {
            float xc = fminf(fmaxf(x[k] * (float)NC, 0.0f), (float)(NC - 1));
            int cell = (int)xc;  // xc >= 0, trunc == floor
            x[k] = fmaf(sT00[cell], x[k], sT01[cell]);
        }
    }

    float* __restrict__ o = out + (size_t)t * (size_t)n_points;
    #pragma unroll
    for (int k = 0; k < PPT; ++k) {
        int idx = base + k * BLOCK;
        if (idx < n_points) o[idx] = x[k];
    }
}

extern "C" void kernel_launch(void* const* d_in, const int* in_sizes, int n_in,
                              void* d_out, int out_size)
{
    const float* points = (const float*)d_in[0];  // [NDIM=1, n_points]
    const float* theta  = (const float*)d_in[1];  // [n_theta, 30]
    const float* basis  = (const float*)d_in[2];  // [64, 30]
    float* out = (float*)d_out;                   // [n_theta, 1, n_points]

    const int n_points = in_sizes[0];             // NDIM == 1
    const int n_theta  = in_sizes[1] / DDIM;

    dim3 grid((n_points + BLOCK * PPT - 1) / (BLOCK * PPT), n_theta);
    cpab_kernel<<<grid, BLOCK>>>(points, theta, basis, out, n_points);
}

// round 2
// speedup vs baseline: 1.0654x; 1.0654x over previous
#include <cuda_runtime.h>
#include <cstdint>

#define NC       32
#define NSTEPS   32
#define DDIM     30
#define BLOCK    256
#define PPT      4    // points per thread

// Shared layout: 4KB alignment slack + T00 table (32 cells x 32 lanes) + T01 table.
// tab0[cell*32 + lane] = T00(cell), tab1 at +4096 bytes. bank(lane) = lane -> conflict-free.
#define TAB_FLOATS   (2 * NC * 32)          // 2048 floats = 8KB
#define SLACK_FLOATS 1024                   // 4KB for runtime 4096-alignment

__global__ __launch_bounds__(BLOCK)
void cpab_kernel(const float* __restrict__ points,
                 const float* __restrict__ theta,
                 const float* __restrict__ basis,
                 float* __restrict__ out,
                 int n_points)
{
    __shared__ float sbuf[TAB_FLOATS + SLACK_FLOATS];
    __shared__ float s0[NC];
    __shared__ float s1[NC];

    const int t    = blockIdx.y;
    const int tid  = threadIdx.x;
    const int lane = tid & 31;

    // Runtime-aligned table base (4096-byte aligned shared address).
    uint32_t sbase = (uint32_t)__cvta_generic_to_shared(sbuf);
    uint32_t abase = (sbase + 4095u) & ~4095u;
    // Per-thread constant: table base | lane*4. Bits [6:2] only -> disjoint
    // from the cell field (bits [11:7]) and from the aligned base (bits >=12).
    uint32_t C = abase + (uint32_t)lane * 4u;

    // --- Per-block: compute 32 cell transforms for this theta ---
    if (tid < NC) {
        const float dT = 1.0f / (float)NSTEPS;
        const float* __restrict__ ba = basis + (2 * tid)     * DDIM;
        const float* __restrict__ bb = basis + (2 * tid + 1) * DDIM;
        const float* __restrict__ th = theta + t * DDIM;
        float a = 0.0f, b = 0.0f;
        #pragma unroll
        for (int j = 0; j < DDIM; ++j) {
            float tj = th[j];
            a = fmaf(ba[j], tj, a);
            b = fmaf(bb[j], tj, b);
        }
        a *= dT;
        b *= dT;
        float ea  = expf(a);
        float phi = (fabsf(a) < 1e-6f) ? (1.0f + 0.5f * a) : (expm1f(a) / a);
        s0[tid] = ea;
        s1[tid] = b * phi;
    }
    __syncthreads();

    // Replicate into 32-lane-wide tables (conflict-free gather layout).
    float* tab = sbuf + ((abase - sbase) >> 2);
    #pragma unroll
    for (int idx = tid; idx < NC * 32; idx += BLOCK) {
        int cell = idx >> 5;
        tab[idx]            = s0[cell];
        tab[NC * 32 + idx]  = s1[cell];
    }
    __syncthreads();

    // --- Main integration ---
    const int base = blockIdx.x * (BLOCK * PPT) + tid;

    float x[PPT];
    #pragma unroll
    for (int k = 0; k < PPT; ++k) {
        int idx = base + k * BLOCK;
        x[k] = (idx < n_points) ? points[idx] : 0.0f;
    }

    #pragma unroll 4
    for (int s = 0; s < NSTEPS; ++s) {
        #pragma unroll
        for (int k = 0; k < PPT; ++k) {
            // bits = 0x4B000000 + floor(x*4096)  (exact: RZ fma, positive range)
            uint32_t bu = __float_as_uint(__fmaf_rz(x[k], 4096.0f, 8388608.0f));
            int bi = (int)bu;
            bi = max(bi, 0x4B000000);   // cell < 0  -> 0
            bi = min(bi, 0x4B000FFF);   // cell > 31 -> 31
            // addr = base | lane*4 | cell*128   (single LOP3)
            uint32_t addr = ((uint32_t)bi & 0x0F80u) | C;
            float t0, t1;
            asm volatile("ld.shared.f32 %0, [%1];"       : "=f"(t0) : "r"(addr));
            asm volatile("ld.shared.f32 %0, [%1+4096];"  : "=f"(t1) : "r"(addr));
            x[k] = fmaf(t0, x[k], t1);
        }
    }

    float* __restrict__ o = out + (size_t)t * (size_t)n_points;
    #pragma unroll
    for (int k = 0; k < PPT; ++k) {
        int idx = base + k * BLOCK;
        if (idx < n_points) o[idx] = x[k];
    }
}

extern "C" void kernel_launch(void* const* d_in, const int* in_sizes, int n_in,
                              void* d_out, int out_size)
{
    const float* points = (const float*)d_in[0];  // [1, n_points]
    const float* theta  = (const float*)d_in[1];  // [n_theta, 30]
    const float* basis  = (const float*)d_in[2];  // [64, 30]
    float* out = (float*)d_out;                   // [n_theta, 1, n_points]

    const int n_points = in_sizes[0];
    const int n_theta  = in_sizes[1] / DDIM;

    dim3 grid((n_points + BLOCK * PPT - 1) / (BLOCK * PPT), n_theta);
    cpab_kernel<<<grid, BLOCK>>>(points, theta, basis, out, n_points);
}